// round 1
// baseline (speedup 1.0000x reference)
#include <cuda_runtime.h>
#include <cuda_bf16.h>
#include <math.h>

// Problem constants
#define B_    32
#define CI    64
#define HH    128
#define WW    128
#define CO    128
#define OH    126
#define OW    126

// Tiling
#define TILE  8              // 8x8 output positions per CTA
#define NT    16             // tiles per dim (16*8 = 128 >= 126)
#define CC    8              // cin per chunk
#define KC    (CC*9)         // 72 k per chunk
#define BS_PAD 132           // padded Bs row (floats)

// scratch: partial pooled sums per (batch, tile, co)
__device__ float g_partial[B_ * NT * NT * CO];

__device__ __forceinline__ float gelu_tanh(float v) {
    const float k0 = 0.7978845608028654f;
    const float c1 = 0.044715f;
    float v3 = v * v * v;
    return 0.5f * v * (1.0f + tanhf(k0 * (v + c1 * v3)));
}

__global__ void __launch_bounds__(256, 2)
conv_gelu_pool_kernel(const float* __restrict__ x,
                      const float* __restrict__ weight,
                      const float* __restrict__ bias)
{
    __shared__ float smem[800 + KC * BS_PAD];   // As: 10*10*8 = 800, Bs: 72*132
    float* As = smem;
    float* Bs = smem + 800;

    const int tid = threadIdx.x;
    const int tx  = blockIdx.x;       // ow tile
    const int ty  = blockIdx.y;       // oh tile
    const int b   = blockIdx.z;

    const int oh0 = ty * TILE;
    const int ow0 = tx * TILE;

    // thread -> (pos group, co group)
    const int pg = tid >> 4;          // 0..15
    const int cg = tid & 15;          // 0..15
    const int py  = pg >> 1;          // 0..7 (row within tile)
    const int pxg = pg & 1;           // 0..1  (4-col group)
    const int co0 = cg * 8;

    float acc[4][8];
#pragma unroll
    for (int i = 0; i < 4; ++i)
#pragma unroll
        for (int j = 0; j < 8; ++j) acc[i][j] = 0.0f;

    const size_t xb = (size_t)b * CI * HH * WW;

    for (int cc = 0; cc < CI / CC; ++cc) {
        // ---- load A tile: [CC][10][10], zero-fill past image edge ----
        for (int idx = tid; idx < CC * 100; idx += 256) {
            int ci  = idx / 100;
            int rem = idx - ci * 100;
            int r   = rem / 10;
            int c   = rem - r * 10;
            int ih  = oh0 + r;
            int iw  = ow0 + c;
            float v = 0.0f;
            if (ih < HH && iw < WW)
                v = x[xb + ((size_t)(cc * CC + ci) * HH + ih) * WW + iw];
            As[idx] = v;
        }
        // ---- load B tile: Bs[kk][co], kk = ci*9+kh*3+kw ----
        // global: weight[co][ci][kh][kw] -> contiguous run of 72 per co
        for (int idx = tid; idx < KC * CO; idx += 256) {
            int co = idx / KC;
            int kk = idx - co * KC;
            Bs[kk * BS_PAD + co] = weight[(size_t)co * (CI * 9) + cc * KC + kk];
        }
        __syncthreads();

        // ---- inner product over this K chunk ----
#pragma unroll
        for (int ci = 0; ci < CC; ++ci) {
#pragma unroll
            for (int kh = 0; kh < 3; ++kh) {
                const float* arow = &As[ci * 100 + (py + kh) * 10 + pxg * 4];
                float ar[6];
#pragma unroll
                for (int t = 0; t < 6; ++t) ar[t] = arow[t];
#pragma unroll
                for (int kw = 0; kw < 3; ++kw) {
                    const int k = ci * 9 + kh * 3 + kw;
                    const float4 b0 = *(const float4*)&Bs[k * BS_PAD + co0];
                    const float4 b1 = *(const float4*)&Bs[k * BS_PAD + co0 + 4];
                    float bv[8] = {b0.x, b0.y, b0.z, b0.w, b1.x, b1.y, b1.z, b1.w};
#pragma unroll
                    for (int i = 0; i < 4; ++i) {
                        const float a = ar[i + kw];
#pragma unroll
                        for (int j = 0; j < 8; ++j)
                            acc[i][j] = fmaf(a, bv[j], acc[i][j]);
                    }
                }
            }
        }
        __syncthreads();
    }

    // ---- epilogue: bias + gelu + partial pool over this thread's positions ----
    const float4 bb0 = *(const float4*)&bias[co0];
    const float4 bb1 = *(const float4*)&bias[co0 + 4];
    const float bv[8] = {bb0.x, bb0.y, bb0.z, bb0.w, bb1.x, bb1.y, bb1.z, bb1.w};

    float pooled[8];
#pragma unroll
    for (int j = 0; j < 8; ++j) pooled[j] = 0.0f;

    const int oh = oh0 + py;
#pragma unroll
    for (int i = 0; i < 4; ++i) {
        const int ow = ow0 + pxg * 4 + i;
        if (oh < OH && ow < OW) {
#pragma unroll
            for (int j = 0; j < 8; ++j)
                pooled[j] += gelu_tanh(acc[i][j] + bv[j]);
        }
    }

    // ---- intra-CTA reduction across 16 position groups (alias smem) ----
    float* red = smem;                 // needs 16*128 = 2048 floats
#pragma unroll
    for (int j = 0; j < 8; ++j) red[pg * CO + co0 + j] = pooled[j];
    __syncthreads();

    if (tid < CO) {
        float s = 0.0f;
#pragma unroll
        for (int p = 0; p < 16; ++p) s += red[p * CO + tid];
        const int tileIdx = ty * NT + tx;
        g_partial[((size_t)b * (NT * NT) + tileIdx) * CO + tid] = s;
    }
}

__global__ void reduce_kernel(float* __restrict__ out)
{
    const int idx = blockIdx.x * blockDim.x + threadIdx.x;  // 0..4095
    const int b  = idx >> 7;
    const int co = idx & 127;
    float s = 0.0f;
    const float* base = &g_partial[(size_t)b * (NT * NT) * CO + co];
#pragma unroll 8
    for (int t = 0; t < NT * NT; ++t) s += base[t * CO];
    out[idx] = s * (1.0f / (float)(OH * OW));
}

extern "C" void kernel_launch(void* const* d_in, const int* in_sizes, int n_in,
                              void* d_out, int out_size)
{
    const float* x      = (const float*)d_in[0];
    const float* weight = (const float*)d_in[1];
    const float* bias   = (const float*)d_in[2];
    float* out = (float*)d_out;

    dim3 grid(NT, NT, B_);
    conv_gelu_pool_kernel<<<grid, 256>>>(x, weight, bias);
    reduce_kernel<<<16, 256>>>(out);
}

// round 3
// speedup vs baseline: 3.2078x; 3.2078x over previous
#include <cuda_runtime.h>
#include <cuda_bf16.h>
#include <math.h>
#include <stdint.h>

// ---------------- problem constants ----------------
#define B_   32
#define CI   64
#define HH   128
#define WW   128
#define HW_  16384
#define OH   126
#define OW   126
#define CO   128
#define KTOT 576
#define NCHK 9
#define XT   33554432L

// ---------------- device scratch ----------------
__device__ __nv_bfloat16 g_xb[B_ * CI * HW_];   // 64 MB bf16 copy of x
__device__ __nv_bfloat16 g_wb[CO * KTOT];       // bf16 weights [co][k]
__device__ float g_partial[B_ * OH * CO];

// ---------------- smem layout ----------------
#define A_STRIDE 144                     // bytes per co row (64 bf16 + pad)
#define B_STRIDE 272                     // bytes per k row (128 bf16 + pad)
#define A_BYTES  (128 * A_STRIDE)        // 18432
#define B_BYTES  (64 * B_STRIDE)         // 17408
#define BUF_BYTES (A_BYTES + B_BYTES)    // 35840
#define SMEM_DYN  (2 * BUF_BYTES)        // 71680

// ---------------- helpers ----------------
__device__ __forceinline__ uint32_t smem_u32(const void* p) {
    uint32_t a;
    asm("{ .reg .u64 t; cvta.to.shared.u64 t, %1; cvt.u32.u64 %0, t; }" : "=r"(a) : "l"(p));
    return a;
}
__device__ __forceinline__ uint32_t pk_bf16x2(float a, float b) {
    __nv_bfloat162 t = __floats2bfloat162_rn(a, b);
    return reinterpret_cast<uint32_t&>(t);
}
__device__ __forceinline__ float gelu_t(float v) {
    float u = 0.7978845608028654f * fmaf(0.044715f * v, v * v, v);
    float t;
    asm("tanh.approx.f32 %0, %1;" : "=f"(t) : "f"(u));
    return 0.5f * v * (1.0f + t);
}

#define LDSM_X4(r, a) \
    asm volatile("ldmatrix.sync.aligned.m8n8.x4.shared.b16 {%0,%1,%2,%3}, [%4];" \
        : "=r"((r)[0]), "=r"((r)[1]), "=r"((r)[2]), "=r"((r)[3]) : "r"(a))
#define LDSM_X2T(r, a) \
    asm volatile("ldmatrix.sync.aligned.m8n8.x2.trans.shared.b16 {%0,%1}, [%2];" \
        : "=r"((r)[0]), "=r"((r)[1]) : "r"(a))
#define MMA16816(d, a, bb) \
    asm volatile("mma.sync.aligned.m16n8k16.row.col.f32.bf16.bf16.f32 " \
        "{%0,%1,%2,%3}, {%4,%5,%6,%7}, {%8,%9}, {%0,%1,%2,%3};" \
        : "+f"((d)[0]), "+f"((d)[1]), "+f"((d)[2]), "+f"((d)[3]) \
        : "r"((a)[0]), "r"((a)[1]), "r"((a)[2]), "r"((a)[3]), "r"((bb)[0]), "r"((bb)[1]))

// ---------------- pre-convert fp32 -> bf16 ----------------
__global__ void cvt_kernel(const float* __restrict__ x, const float* __restrict__ w)
{
    long i = (long)blockIdx.x * blockDim.x + threadIdx.x;
    long base = i * 8;
    {   // x: 33554432 elems, grid covers exactly
        const float4* xf = (const float4*)(x + base);
        float4 v0 = xf[0], v1 = xf[1];
        uint4 o;
        o.x = pk_bf16x2(v0.x, v0.y);
        o.y = pk_bf16x2(v0.z, v0.w);
        o.z = pk_bf16x2(v1.x, v1.y);
        o.w = pk_bf16x2(v1.z, v1.w);
        *(uint4*)(g_xb + base) = o;
    }
    if (base < CO * KTOT) {  // weights: 73728 elems
        const float4* wf = (const float4*)(w + base);
        float4 v0 = wf[0], v1 = wf[1];
        uint4 o;
        o.x = pk_bf16x2(v0.x, v0.y);
        o.y = pk_bf16x2(v0.z, v0.w);
        o.z = pk_bf16x2(v1.x, v1.y);
        o.w = pk_bf16x2(v1.z, v1.w);
        *(uint4*)(g_wb + base) = o;
    }
}

// ---------------- main conv kernel ----------------
__global__ void __launch_bounds__(256, 2)
conv_mma_kernel(const float* __restrict__ bias)
{
    extern __shared__ char smem[];
    const int tid  = threadIdx.x;
    const int wid  = tid >> 5;
    const int lane = tid & 31;
    const int oh   = blockIdx.x;
    const int b    = blockIdx.y;
    const __nv_bfloat16* xb = g_xb + (long)b * CI * HW_;
    const __nv_bfloat16* xend = g_xb + XT;

    const uint32_t sbase = smem_u32(smem);

    const int mg = wid & 1;        // M group: co 0-63 / 64-127
    const int ng = wid >> 1;       // N group: pos 32-block

    float acc[4][4][4];
#pragma unroll
    for (int mf = 0; mf < 4; ++mf)
#pragma unroll
        for (int nf = 0; nf < 4; ++nf)
#pragma unroll
            for (int e = 0; e < 4; ++e) acc[mf][nf][e] = 0.0f;

    // ---- tile loaders ----
    auto loadA = [&](int c, char* dst) {
#pragma unroll
        for (int it = 0; it < 4; ++it) {
            int idx = tid + it * 256;           // 0..1023
            int co  = idx >> 3;
            int q   = idx & 7;
            uint4 v = *(const uint4*)((const char*)g_wb + co * (KTOT * 2) + c * 128 + q * 16);
            *(uint4*)(dst + co * A_STRIDE + q * 16) = v;
        }
    };
    auto loadB = [&](int c, char* dst) {
#pragma unroll
        for (int it = 0; it < 16; ++it) {
            int idx = tid + it * 256;           // 0..4095
            int kk  = idx >> 6;
            int j   = idx & 63;                 // u32 slot = pos 2j,2j+1
            int k   = c * 64 + kk;
            int ci  = k / 9;
            int r   = k - ci * 9;
            int kh  = r / 3;
            int kw  = r - kh * 3;
            const __nv_bfloat16* p = xb + ci * HW_ + (oh + kh) * WW + kw + 2 * j;
            uint32_t v;
            if (p + 1 < xend) {
                if (kw == 1) {
                    uint16_t lo = *(const uint16_t*)p;
                    uint16_t hi = *(const uint16_t*)(p + 1);
                    v = (uint32_t)lo | ((uint32_t)hi << 16);
                } else {
                    v = *(const uint32_t*)p;    // kw 0/2 -> 4B aligned
                }
            } else {
                uint16_t lo = (p < xend) ? *(const uint16_t*)p : 0;
                v = (uint32_t)lo;
            }
            *(uint32_t*)(dst + kk * B_STRIDE + j * 4) = v;
        }
    };

    char* tiles = smem;
    loadA(0, tiles);
    loadB(0, tiles + A_BYTES);
    __syncthreads();

    // ldsm base addresses (per-warp constants)
    const uint32_t aCoBase = sbase + (mg * 64 + (lane & 15)) * A_STRIDE + (lane >> 4) * 16;
    const uint32_t bKBase  = sbase + A_BYTES + (lane & 15) * B_STRIDE + ng * 64;

#pragma unroll 1
    for (int c = 0; c < NCHK; ++c) {
        const uint32_t cur = (uint32_t)(c & 1) * BUF_BYTES;
        char* nxt = tiles + (((c & 1) ^ 1) ? BUF_BYTES : 0);

        // ---- compute current chunk ----
#pragma unroll
        for (int s = 0; s < 4; ++s) {
            uint32_t afr[4][4], bfr[4][2];
#pragma unroll
            for (int mf = 0; mf < 4; ++mf)
                LDSM_X4(afr[mf], aCoBase + cur + mf * 16 * A_STRIDE + s * 32);
#pragma unroll
            for (int nf = 0; nf < 4; ++nf)
                LDSM_X2T(bfr[nf], bKBase + cur + s * 16 * B_STRIDE + nf * 16);
#pragma unroll
            for (int mf = 0; mf < 4; ++mf)
#pragma unroll
                for (int nf = 0; nf < 4; ++nf)
                    MMA16816(acc[mf][nf], afr[mf], bfr[nf]);
        }

        // ---- load next chunk ----
        if (c + 1 < NCHK) {
            loadA(c + 1, nxt);
            loadB(c + 1, nxt + A_BYTES);
        }
        __syncthreads();
    }

    // ---- epilogue: bias + gelu + pool (pos<126) ----
    float* red = (float*)smem;               // 512 floats, tiles dead
    const int rr = lane >> 2;
    const int q  = lane & 3;
#pragma unroll
    for (int mf = 0; mf < 4; ++mf) {
#pragma unroll
        for (int half = 0; half < 2; ++half) {
            const int co = mg * 64 + mf * 16 + half * 8 + rr;
            const float bv = __ldg(bias + co);
            float s = 0.0f;
#pragma unroll
            for (int nf = 0; nf < 4; ++nf) {
#pragma unroll
                for (int e = 0; e < 2; ++e) {
                    const int pos = ng * 32 + nf * 8 + q * 2 + e;
                    const float v = acc[mf][nf][half * 2 + e] + bv;
                    if (pos < OW) s += gelu_t(v);
                }
            }
            s += __shfl_xor_sync(0xFFFFFFFFu, s, 1);
            s += __shfl_xor_sync(0xFFFFFFFFu, s, 2);
            if (q == 0) red[ng * CO + co] = s;
        }
    }
    __syncthreads();
    if (tid < CO) {
        float s = red[tid] + red[CO + tid] + red[2 * CO + tid] + red[3 * CO + tid];
        g_partial[((long)b * OH + oh) * CO + tid] = s;
    }
}

// ---------------- final reduction ----------------
__global__ void reduce_kernel(float* __restrict__ out)
{
    __shared__ float sred[512];
    const int b   = blockIdx.x;
    const int co  = threadIdx.x & 127;
    const int seg = threadIdx.x >> 7;
    const float* p = g_partial + (long)b * OH * CO + co;
    const int o0 = seg * 32;
    const int o1 = (o0 + 32 < OH) ? (o0 + 32) : OH;
    float s = 0.0f;
    for (int t = o0; t < o1; ++t) s += p[t * CO];
    sred[threadIdx.x] = s;
    __syncthreads();
    if (threadIdx.x < 128) {
        float r = sred[threadIdx.x] + sred[threadIdx.x + 128]
                + sred[threadIdx.x + 256] + sred[threadIdx.x + 384];
        out[b * CO + threadIdx.x] = r * (1.0f / (float)(OH * OW));
    }
}

extern "C" void kernel_launch(void* const* d_in, const int* in_sizes, int n_in,
                              void* d_out, int out_size)
{
    const float* x      = (const float*)d_in[0];
    const float* weight = (const float*)d_in[1];
    const float* bias   = (const float*)d_in[2];
    float* out = (float*)d_out;

    cudaFuncSetAttribute(conv_mma_kernel,
                         cudaFuncAttributeMaxDynamicSharedMemorySize, SMEM_DYN);

    cvt_kernel<<<16384, 256>>>(x, weight);
    conv_mma_kernel<<<dim3(OH, B_), 256, SMEM_DYN>>>(bias);
    reduce_kernel<<<32, 512>>>(out);
}

// round 4
// speedup vs baseline: 6.9534x; 2.1677x over previous
#include <cuda_runtime.h>
#include <cuda_bf16.h>
#include <math.h>
#include <stdint.h>

// ---------------- problem constants ----------------
#define B_   32
#define CI   64
#define HH   128
#define WW   128
#define HW_  16384
#define OH   126
#define OW   126
#define CO   128
#define KTOT 576
#define KCH  72
#define NCHK 8
#define XT   33554432L

// ---------------- device scratch ----------------
__device__ __nv_bfloat16 g_xb[B_ * CI * HW_ + 16];  // bf16 x (+pad)
__device__ __nv_bfloat16 g_xs[B_ * CI * HW_ + 16];  // bf16 x shifted by +1 elem
__device__ __nv_bfloat16 g_wb[CO * KTOT];           // bf16 weights [co][k]
__device__ float g_partial[B_ * OH * CO];

// ---------------- smem layout ----------------
#define A_STRIDE 144                       // 72 bf16 per co row, no pad (conflict-free)
#define B_STRIDE 272                       // 128 bf16 + 16B pad per k row
#define A_BYTES  (128 * A_STRIDE)          // 18432
#define B_BYTES  (KCH * B_STRIDE)          // 19584
#define BUF_BYTES (A_BYTES + B_BYTES)      // 38016
#define TILE0    1024                      // buffers start (table lives below)
#define SMEM_DYN (TILE0 + 2 * BUF_BYTES)   // 77056

// ---------------- helpers ----------------
__device__ __forceinline__ uint32_t smem_u32(const void* p) {
    uint32_t a;
    asm("{ .reg .u64 t; cvta.to.shared.u64 t, %1; cvt.u32.u64 %0, t; }" : "=r"(a) : "l"(p));
    return a;
}
__device__ __forceinline__ uint64_t to_global(const void* p) {
    uint64_t g;
    asm("cvta.to.global.u64 %0, %1;" : "=l"(g) : "l"(p));
    return g;
}
__device__ __forceinline__ uint32_t pk_bf16x2(float a, float b) {
    __nv_bfloat162 t = __floats2bfloat162_rn(a, b);
    return reinterpret_cast<uint32_t&>(t);
}
__device__ __forceinline__ float gelu_t(float v) {
    float u = 0.7978845608028654f * fmaf(0.044715f * v, v * v, v);
    float t;
    asm("tanh.approx.f32 %0, %1;" : "=f"(t) : "f"(u));
    return 0.5f * v * (1.0f + t);
}

#define CP4(dst, src)  asm volatile("cp.async.ca.shared.global [%0], [%1], 4;"  :: "r"(dst), "l"(src))
#define CP16(dst, src) asm volatile("cp.async.ca.shared.global [%0], [%1], 16;" :: "r"(dst), "l"(src))
#define CP_COMMIT()    asm volatile("cp.async.commit_group;" ::: "memory")
#define CP_WAIT1()     asm volatile("cp.async.wait_group 1;" ::: "memory")
#define CP_WAIT0()     asm volatile("cp.async.wait_group 0;" ::: "memory")

#define LDSM_X4(r, a) \
    asm volatile("ldmatrix.sync.aligned.m8n8.x4.shared.b16 {%0,%1,%2,%3}, [%4];" \
        : "=r"((r)[0]), "=r"((r)[1]), "=r"((r)[2]), "=r"((r)[3]) : "r"(a))
#define LDSM_X2(r, a) \
    asm volatile("ldmatrix.sync.aligned.m8n8.x2.shared.b16 {%0,%1}, [%2];" \
        : "=r"((r)[0]), "=r"((r)[1]) : "r"(a))
#define LDSM_X2T(r, a) \
    asm volatile("ldmatrix.sync.aligned.m8n8.x2.trans.shared.b16 {%0,%1}, [%2];" \
        : "=r"((r)[0]), "=r"((r)[1]) : "r"(a))
#define LDSM_X1T(r, a) \
    asm volatile("ldmatrix.sync.aligned.m8n8.x1.trans.shared.b16 {%0}, [%1];" \
        : "=r"((r)[0]) : "r"(a))
#define MMA16816(d, a, bb) \
    asm volatile("mma.sync.aligned.m16n8k16.row.col.f32.bf16.bf16.f32 " \
        "{%0,%1,%2,%3}, {%4,%5,%6,%7}, {%8,%9}, {%0,%1,%2,%3};" \
        : "+f"((d)[0]), "+f"((d)[1]), "+f"((d)[2]), "+f"((d)[3]) \
        : "r"((a)[0]), "r"((a)[1]), "r"((a)[2]), "r"((a)[3]), "r"((bb)[0]), "r"((bb)[1]))
#define MMA1688(d, a, bb) \
    asm volatile("mma.sync.aligned.m16n8k8.row.col.f32.bf16.bf16.f32 " \
        "{%0,%1,%2,%3}, {%4,%5}, {%6}, {%0,%1,%2,%3};" \
        : "+f"((d)[0]), "+f"((d)[1]), "+f"((d)[2]), "+f"((d)[3]) \
        : "r"((a)[0]), "r"((a)[1]), "r"((bb)[0]))

// ---------------- pre-convert fp32 -> bf16 (+shifted copy) ----------------
__global__ void cvt_kernel(const float* __restrict__ x, const float* __restrict__ w)
{
    long i = (long)blockIdx.x * blockDim.x + threadIdx.x;
    long base = i * 8;
    {
        const float4* xf = (const float4*)(x + base);
        float4 v0 = xf[0], v1 = xf[1];
        float tail = (base + 8 < XT) ? __ldg(x + base + 8) : 0.0f;
        uint4 o;
        o.x = pk_bf16x2(v0.x, v0.y);
        o.y = pk_bf16x2(v0.z, v0.w);
        o.z = pk_bf16x2(v1.x, v1.y);
        o.w = pk_bf16x2(v1.z, v1.w);
        *(uint4*)(g_xb + base) = o;
        uint4 s;
        s.x = pk_bf16x2(v0.y, v0.z);
        s.y = pk_bf16x2(v0.w, v1.x);
        s.z = pk_bf16x2(v1.y, v1.z);
        s.w = pk_bf16x2(v1.w, tail);
        *(uint4*)(g_xs + base) = s;
    }
    if (base < CO * KTOT) {
        const float4* wf = (const float4*)(w + base);
        float4 v0 = wf[0], v1 = wf[1];
        uint4 o;
        o.x = pk_bf16x2(v0.x, v0.y);
        o.y = pk_bf16x2(v0.z, v0.w);
        o.z = pk_bf16x2(v1.x, v1.y);
        o.w = pk_bf16x2(v1.z, v1.w);
        *(uint4*)(g_wb + base) = o;
    }
}

// ---------------- main conv kernel ----------------
__global__ void __launch_bounds__(256, 2)
conv_mma_kernel(const float* __restrict__ bias)
{
    extern __shared__ char smem[];
    const int tid  = threadIdx.x;
    const int wid  = tid >> 5;
    const int lane = tid & 31;
    const int oh   = blockIdx.x;
    const int b    = blockIdx.y;

    const uint32_t sbase = smem_u32(smem);
    uint64_t* tab = (uint64_t*)smem;          // 72 entries

    // build pointer table: tab[kk] = global base for (ci_local, kh, kw)
    if (tid < KCH) {
        int kk = tid;
        int ci = kk / 9;
        int r  = kk - 9 * ci;
        int kh = r / 3;
        int kw = r - 3 * kh;
        const __nv_bfloat16* p = ((kw == 1) ? g_xs : g_xb)
                               + ci * HW_ + kh * WW + ((kw == 2) ? 2 : 0);
        tab[kk] = to_global(p);
    }

    const int mg = wid & 1;        // M group: co 0-63 / 64-127
    const int ng = wid >> 1;       // N group: 32-pos block

    float acc[4][4][4];
#pragma unroll
    for (int mf = 0; mf < 4; ++mf)
#pragma unroll
        for (int nf = 0; nf < 4; ++nf)
#pragma unroll
            for (int e = 0; e < 4; ++e) acc[mf][nf][e] = 0.0f;

    // per-thread constants for loaders
    const uint64_t gw  = to_global(g_wb);
    const int j   = tid & 63;                 // u32 slot within k row (pos pair)
    const int tg  = tid >> 6;
    const uint64_t srcDelta0 = ((uint64_t)((long)b * CI * HW_ + (long)oh * WW + 2 * j)) * 2;
    const uint32_t tabAddr   = sbase + tg * 8;
    const uint32_t dstB0     = sbase + TILE0 + A_BYTES + tg * B_STRIDE + j * 4;
    // A loader mapping (5 guarded iterations over 1152 16B segs)
    const uint32_t dstA0 = sbase + TILE0;

    __syncthreads();   // table visible

    auto load_chunk = [&](int c, int buf) {
        const uint32_t bufOff = (uint32_t)buf * BUF_BYTES;
        // A: weights [co][c*144 .. +144) bytes, 1152 16B segs
#pragma unroll
        for (int rr = 0; rr < 5; ++rr) {
            int s = tid + rr * 256;
            if (s < 1152) {
                int co = s / 9;
                int q  = s - 9 * co;
                uint64_t src = gw + (uint64_t)co * (KTOT * 2) + (uint64_t)c * (KCH * 2) + q * 16;
                uint32_t dst = dstA0 + bufOff + co * A_STRIDE + q * 16;
                CP16(dst, src);
            }
        }
        // B: 72 k rows x 64 u32 slots, kk = tg + 4*rr
        const uint64_t srcDelta = srcDelta0 + (uint64_t)c * (8 * HW_ * 2);
        uint32_t dst = dstB0 + bufOff;
        uint32_t ta  = tabAddr;
#pragma unroll
        for (int rr = 0; rr < 18; ++rr) {
            uint64_t base;
            asm volatile("ld.shared.b64 %0, [%1];" : "=l"(base) : "r"(ta));
            CP4(dst, base + srcDelta);
            dst += 4 * B_STRIDE;
            ta  += 32;
        }
    };

    load_chunk(0, 0); CP_COMMIT();
    load_chunk(1, 1); CP_COMMIT();

    // ldsm base addresses (per-warp constants)
    const uint32_t aCoBase = sbase + TILE0 + (mg * 64 + (lane & 15)) * A_STRIDE + (lane >> 4) * 16;
    const uint32_t bKBase  = sbase + TILE0 + A_BYTES + (lane & 15) * B_STRIDE + ng * 64;

#pragma unroll 1
    for (int c = 0; c < NCHK; ++c) {
        if (c < NCHK - 1) { CP_WAIT1(); } else { CP_WAIT0(); }
        __syncthreads();

        const uint32_t cur = (uint32_t)(c & 1) * BUF_BYTES;
        // 4 full k16 steps
#pragma unroll
        for (int s = 0; s < 4; ++s) {
            uint32_t afr[4][4], bfr[4][2];
#pragma unroll
            for (int mf = 0; mf < 4; ++mf)
                LDSM_X4(afr[mf], aCoBase + cur + mf * 16 * A_STRIDE + s * 32);
#pragma unroll
            for (int nf = 0; nf < 4; ++nf)
                LDSM_X2T(bfr[nf], bKBase + cur + s * 16 * B_STRIDE + nf * 16);
#pragma unroll
            for (int mf = 0; mf < 4; ++mf)
#pragma unroll
                for (int nf = 0; nf < 4; ++nf)
                    MMA16816(acc[mf][nf], afr[mf], bfr[nf]);
        }
        // trailing k8 step (k = 64..71)
        {
            uint32_t afr[4][2], bfr[4][1];
#pragma unroll
            for (int mf = 0; mf < 4; ++mf)
                LDSM_X2(afr[mf], aCoBase + cur + mf * 16 * A_STRIDE + 128);
#pragma unroll
            for (int nf = 0; nf < 4; ++nf)
                LDSM_X1T(bfr[nf], bKBase + cur + 64 * B_STRIDE + nf * 16);
#pragma unroll
            for (int mf = 0; mf < 4; ++mf)
#pragma unroll
                for (int nf = 0; nf < 4; ++nf)
                    MMA1688(acc[mf][nf], afr[mf], bfr[nf]);
        }
        __syncthreads();
        if (c + 2 < NCHK) { load_chunk(c + 2, c & 1); CP_COMMIT(); }
    }

    // ---- epilogue: bias + gelu + pool (pos < 126) ----
    float* red = (float*)smem;               // 512 floats; tiles/table dead
    const int rr = lane >> 2;
    const int q  = lane & 3;
#pragma unroll
    for (int mf = 0; mf < 4; ++mf) {
#pragma unroll
        for (int half = 0; half < 2; ++half) {
            const int co = mg * 64 + mf * 16 + half * 8 + rr;
            const float bv = __ldg(bias + co);
            float s = 0.0f;
#pragma unroll
            for (int nf = 0; nf < 4; ++nf) {
#pragma unroll
                for (int e = 0; e < 2; ++e) {
                    const int pos = ng * 32 + nf * 8 + q * 2 + e;
                    const float v = acc[mf][nf][half * 2 + e] + bv;
                    if (pos < OW) s += gelu_t(v);
                }
            }
            s += __shfl_xor_sync(0xFFFFFFFFu, s, 1);
            s += __shfl_xor_sync(0xFFFFFFFFu, s, 2);
            if (q == 0) red[ng * CO + co] = s;
        }
    }
    __syncthreads();
    if (tid < CO) {
        float s = red[tid] + red[CO + tid] + red[2 * CO + tid] + red[3 * CO + tid];
        g_partial[((long)b * OH + oh) * CO + tid] = s;
    }
}

// ---------------- final reduction ----------------
__global__ void reduce_kernel(float* __restrict__ out)
{
    __shared__ float sred[512];
    const int b   = blockIdx.x;
    const int co  = threadIdx.x & 127;
    const int seg = threadIdx.x >> 7;
    const float* p = g_partial + (long)b * OH * CO + co;
    const int o0 = seg * 32;
    const int o1 = (o0 + 32 < OH) ? (o0 + 32) : OH;
    float s = 0.0f;
    for (int t = o0; t < o1; ++t) s += p[t * CO];
    sred[threadIdx.x] = s;
    __syncthreads();
    if (threadIdx.x < 128) {
        float r = sred[threadIdx.x] + sred[threadIdx.x + 128]
                + sred[threadIdx.x + 256] + sred[threadIdx.x + 384];
        out[b * CO + threadIdx.x] = r * (1.0f / (float)(OH * OW));
    }
}

extern "C" void kernel_launch(void* const* d_in, const int* in_sizes, int n_in,
                              void* d_out, int out_size)
{
    const float* x      = (const float*)d_in[0];
    const float* weight = (const float*)d_in[1];
    const float* bias   = (const float*)d_in[2];
    float* out = (float*)d_out;

    cudaFuncSetAttribute(conv_mma_kernel,
                         cudaFuncAttributeMaxDynamicSharedMemorySize, SMEM_DYN);

    cvt_kernel<<<16384, 256>>>(x, weight);
    conv_mma_kernel<<<dim3(OH, B_), 256, SMEM_DYN>>>(bias);
    reduce_kernel<<<32, 512>>>(out);
}

// round 5
// speedup vs baseline: 7.2075x; 1.0365x over previous
#include <cuda_runtime.h>
#include <cuda_fp16.h>
#include <math.h>
#include <stdint.h>

// ---------------- problem constants ----------------
#define B_   32
#define CI   64
#define HH   128
#define WW   128
#define HW_  16384
#define OH   126
#define OW   126
#define CO   128
#define KTOT 576
#define KCH  64
#define NCHK 9
#define XT   33554432L

// ---------------- device scratch ----------------
__device__ __half g_xh [B_ * CI * HW_ + 16];  // fp16 x (+pad)
__device__ __half g_xsh[B_ * CI * HW_ + 16];  // fp16 x shifted by +1 elem
__device__ __half g_wh [CO * KTOT];           // fp16 weights [co][k]
__device__ float  g_partial[B_ * OH * CO];

// ---------------- smem layout ----------------
#define A_STRIDE 144                       // 64 fp16 (128B) + 16B pad
#define B_STRIDE 272                       // 128 fp16 + 16B pad per k row
#define A_BYTES  (128 * A_STRIDE)          // 18432
#define B_BYTES  (KCH * B_STRIDE)          // 17408
#define BUF_BYTES (A_BYTES + B_BYTES)      // 35840
#define TILE0    4736                      // 576*8 table + pad
#define SMEM_DYN (TILE0 + 2 * BUF_BYTES)   // 76416

// ---------------- helpers ----------------
__device__ __forceinline__ uint32_t smem_u32(const void* p) {
    uint32_t a;
    asm("{ .reg .u64 t; cvta.to.shared.u64 t, %1; cvt.u32.u64 %0, t; }" : "=r"(a) : "l"(p));
    return a;
}
__device__ __forceinline__ uint64_t to_global(const void* p) {
    uint64_t g;
    asm("cvta.to.global.u64 %0, %1;" : "=l"(g) : "l"(p));
    return g;
}
__device__ __forceinline__ uint32_t pk_f16x2(float a, float b) {
    __half2 t = __floats2half2_rn(a, b);
    return reinterpret_cast<uint32_t&>(t);
}
__device__ __forceinline__ float gelu_t(float v) {
    float u = 0.7978845608028654f * fmaf(0.044715f * v, v * v, v);
    float t;
    asm("tanh.approx.f32 %0, %1;" : "=f"(t) : "f"(u));
    return 0.5f * v * (1.0f + t);
}

#define CP4(dst, src)  asm volatile("cp.async.ca.shared.global [%0], [%1], 4;"  :: "r"(dst), "l"(src))
#define CP16(dst, src) asm volatile("cp.async.ca.shared.global [%0], [%1], 16;" :: "r"(dst), "l"(src))
#define CP_COMMIT()    asm volatile("cp.async.commit_group;" ::: "memory")
#define CP_WAIT1()     asm volatile("cp.async.wait_group 1;" ::: "memory")
#define CP_WAIT0()     asm volatile("cp.async.wait_group 0;" ::: "memory")

#define LDSM_X4(r, a) \
    asm volatile("ldmatrix.sync.aligned.m8n8.x4.shared.b16 {%0,%1,%2,%3}, [%4];" \
        : "=r"((r)[0]), "=r"((r)[1]), "=r"((r)[2]), "=r"((r)[3]) : "r"(a))
#define LDSM_X2T(r, a) \
    asm volatile("ldmatrix.sync.aligned.m8n8.x2.trans.shared.b16 {%0,%1}, [%2];" \
        : "=r"((r)[0]), "=r"((r)[1]) : "r"(a))
// fp16 accumulate MMA: D,C are 2x f16x2 regs
#define MMA16816H(d, a, bb) \
    asm volatile("mma.sync.aligned.m16n8k16.row.col.f16.f16.f16.f16 " \
        "{%0,%1}, {%2,%3,%4,%5}, {%6,%7}, {%0,%1};" \
        : "+r"((d)[0]), "+r"((d)[1]) \
        : "r"((a)[0]), "r"((a)[1]), "r"((a)[2]), "r"((a)[3]), "r"((bb)[0]), "r"((bb)[1]))

// ---------------- pre-convert fp32 -> fp16 (+shifted copy) ----------------
__global__ void cvt_kernel(const float* __restrict__ x, const float* __restrict__ w)
{
    long i = (long)blockIdx.x * blockDim.x + threadIdx.x;
    long base = i * 8;
    {
        const float4* xf = (const float4*)(x + base);
        float4 v0 = xf[0], v1 = xf[1];
        float tail = (base + 8 < XT) ? __ldg(x + base + 8) : 0.0f;
        uint4 o;
        o.x = pk_f16x2(v0.x, v0.y);
        o.y = pk_f16x2(v0.z, v0.w);
        o.z = pk_f16x2(v1.x, v1.y);
        o.w = pk_f16x2(v1.z, v1.w);
        *(uint4*)(g_xh + base) = o;
        uint4 s;
        s.x = pk_f16x2(v0.y, v0.z);
        s.y = pk_f16x2(v0.w, v1.x);
        s.z = pk_f16x2(v1.y, v1.z);
        s.w = pk_f16x2(v1.w, tail);
        *(uint4*)(g_xsh + base) = s;
    }
    if (base < CO * KTOT) {
        const float4* wf = (const float4*)(w + base);
        float4 v0 = wf[0], v1 = wf[1];
        uint4 o;
        o.x = pk_f16x2(v0.x, v0.y);
        o.y = pk_f16x2(v0.z, v0.w);
        o.z = pk_f16x2(v1.x, v1.y);
        o.w = pk_f16x2(v1.z, v1.w);
        *(uint4*)(g_wh + base) = o;
    }
}

// ---------------- main conv kernel ----------------
__global__ void __launch_bounds__(256, 2)
conv_mma_kernel(const float* __restrict__ bias)
{
    extern __shared__ char smem[];
    const int tid  = threadIdx.x;
    const int wid  = tid >> 5;
    const int lane = tid & 31;
    const int oh   = blockIdx.x;
    const int b    = blockIdx.y;

    const uint32_t sbase = smem_u32(smem);
    uint64_t* tab = (uint64_t*)smem;          // 576 entries, absolute k

    // build pointer table: tab[k] = global base for (ci, kh, kw)
    for (int t = tid; t < KTOT; t += 256) {
        int ci = t / 9;
        int r  = t - 9 * ci;
        int kh = r / 3;
        int kw = r - 3 * kh;
        const __half* p = ((kw == 1) ? g_xsh : g_xh)
                        + ci * HW_ + kh * WW + ((kw == 2) ? 2 : 0);
        tab[t] = to_global(p);
    }

    const int mg = wid & 1;        // M group: co 0-63 / 64-127
    const int ng = wid >> 1;       // N group: 32-pos block

    float acc[4][4][4];
#pragma unroll
    for (int mf = 0; mf < 4; ++mf)
#pragma unroll
        for (int nf = 0; nf < 4; ++nf)
#pragma unroll
            for (int e = 0; e < 4; ++e) acc[mf][nf][e] = 0.0f;

    // per-thread constants for loaders
    const uint64_t gw  = to_global(g_wh);
    const int j   = tid & 63;                 // u32 slot within k row (pos pair)
    const int tg  = tid >> 6;
    const uint64_t srcDelta = ((uint64_t)((long)b * CI * HW_ + (long)oh * WW + 2 * j)) * 2;
    const uint32_t tabAddr  = sbase + tg * 8;
    const uint32_t dstB0    = sbase + TILE0 + A_BYTES + tg * B_STRIDE + j * 4;
    const uint32_t dstA0    = sbase + TILE0;

    __syncthreads();   // table visible

    auto load_chunk = [&](int c, int buf) {
        const uint32_t bufOff = (uint32_t)buf * BUF_BYTES;
        // A: weights [co][c*64 .. +64) fp16 = 128B per co, 1024 16B segs
#pragma unroll
        for (int rr = 0; rr < 4; ++rr) {
            int s = tid + rr * 256;
            int co = s >> 3;
            int q  = s & 7;
            uint64_t src = gw + (uint64_t)co * (KTOT * 2) + (uint64_t)c * (KCH * 2) + q * 16;
            uint32_t dst = dstA0 + bufOff + co * A_STRIDE + q * 16;
            CP16(dst, src);
        }
        // B: 64 k rows x 64 u32 slots, kk = tg + 4*rr
        uint32_t dst = dstB0 + bufOff;
        uint32_t ta  = tabAddr + (uint32_t)c * (KCH * 8);
#pragma unroll
        for (int rr = 0; rr < 16; ++rr) {
            uint64_t base;
            asm volatile("ld.shared.b64 %0, [%1];" : "=l"(base) : "r"(ta));
            CP4(dst, base + srcDelta);
            dst += 4 * B_STRIDE;
            ta  += 32;
        }
    };

    load_chunk(0, 0); CP_COMMIT();
    load_chunk(1, 1); CP_COMMIT();

    // ldsm base addresses (per-warp constants)
    const uint32_t aCoBase = sbase + TILE0 + (mg * 64 + (lane & 15)) * A_STRIDE + (lane >> 4) * 16;
    const uint32_t bKBase  = sbase + TILE0 + A_BYTES + (lane & 15) * B_STRIDE + ng * 64;

#pragma unroll 1
    for (int c = 0; c < NCHK; ++c) {
        if (c < NCHK - 1) { CP_WAIT1(); } else { CP_WAIT0(); }
        __syncthreads();

        const uint32_t cur = (uint32_t)(c & 1) * BUF_BYTES;

        // fresh f16 accumulators for this chunk
        uint32_t hd[4][4][2];
#pragma unroll
        for (int mf = 0; mf < 4; ++mf)
#pragma unroll
            for (int nf = 0; nf < 4; ++nf) { hd[mf][nf][0] = 0u; hd[mf][nf][1] = 0u; }

#pragma unroll
        for (int s = 0; s < 4; ++s) {
            uint32_t afr[4][4], bfr[4][2];
#pragma unroll
            for (int mf = 0; mf < 4; ++mf)
                LDSM_X4(afr[mf], aCoBase + cur + mf * 16 * A_STRIDE + s * 32);
#pragma unroll
            for (int nf = 0; nf < 4; ++nf)
                LDSM_X2T(bfr[nf], bKBase + cur + s * 16 * B_STRIDE + nf * 16);
#pragma unroll
            for (int mf = 0; mf < 4; ++mf)
#pragma unroll
                for (int nf = 0; nf < 4; ++nf)
                    MMA16816H(hd[mf][nf], afr[mf], bfr[nf]);
        }
        __syncthreads();
        if (c + 2 < NCHK) { load_chunk(c + 2, c & 1); CP_COMMIT(); }

        // promote chunk f16 accum -> f32 (overlaps prefetch LDGSTS)
#pragma unroll
        for (int mf = 0; mf < 4; ++mf)
#pragma unroll
            for (int nf = 0; nf < 4; ++nf) {
                float2 lo = __half22float2(*(const __half2*)&hd[mf][nf][0]);
                float2 hi = __half22float2(*(const __half2*)&hd[mf][nf][1]);
                acc[mf][nf][0] += lo.x;
                acc[mf][nf][1] += lo.y;
                acc[mf][nf][2] += hi.x;
                acc[mf][nf][3] += hi.y;
            }
    }

    // ---- epilogue: bias + gelu + pool (pos < 126) ----
    float* red = (float*)smem;               // 512 floats; tiles/table dead
    const int rr = lane >> 2;
    const int q  = lane & 3;
#pragma unroll
    for (int mf = 0; mf < 4; ++mf) {
#pragma unroll
        for (int half = 0; half < 2; ++half) {
            const int co = mg * 64 + mf * 16 + half * 8 + rr;
            const float bv = __ldg(bias + co);
            float s = 0.0f;
#pragma unroll
            for (int nf = 0; nf < 4; ++nf) {
#pragma unroll
                for (int e = 0; e < 2; ++e) {
                    const int pos = ng * 32 + nf * 8 + q * 2 + e;
                    const float v = acc[mf][nf][half * 2 + e] + bv;
                    if (pos < OW) s += gelu_t(v);
                }
            }
            s += __shfl_xor_sync(0xFFFFFFFFu, s, 1);
            s += __shfl_xor_sync(0xFFFFFFFFu, s, 2);
            if (q == 0) red[ng * CO + co] = s;
        }
    }
    __syncthreads();
    if (tid < CO) {
        float s = red[tid] + red[CO + tid] + red[2 * CO + tid] + red[3 * CO + tid];
        g_partial[((long)b * OH + oh) * CO + tid] = s;
    }
}

// ---------------- final reduction ----------------
__global__ void reduce_kernel(float* __restrict__ out)
{
    __shared__ float sred[512];
    const int b   = blockIdx.x;
    const int co  = threadIdx.x & 127;
    const int seg = threadIdx.x >> 7;
    const float* p = g_partial + (long)b * OH * CO + co;
    const int o0 = seg * 32;
    const int o1 = (o0 + 32 < OH) ? (o0 + 32) : OH;
    float s = 0.0f;
    for (int t = o0; t < o1; ++t) s += p[t * CO];
    sred[threadIdx.x] = s;
    __syncthreads();
    if (threadIdx.x < 128) {
        float r = sred[threadIdx.x] + sred[threadIdx.x + 128]
                + sred[threadIdx.x + 256] + sred[threadIdx.x + 384];
        out[b * CO + threadIdx.x] = r * (1.0f / (float)(OH * OW));
    }
}

extern "C" void kernel_launch(void* const* d_in, const int* in_sizes, int n_in,
                              void* d_out, int out_size)
{
    const float* x      = (const float*)d_in[0];
    const float* weight = (const float*)d_in[1];
    const float* bias   = (const float*)d_in[2];
    float* out = (float*)d_out;

    cudaFuncSetAttribute(conv_mma_kernel,
                         cudaFuncAttributeMaxDynamicSharedMemorySize, SMEM_DYN);

    cvt_kernel<<<16384, 256>>>(x, weight);
    conv_mma_kernel<<<dim3(OH, B_), 256, SMEM_DYN>>>(bias);
    reduce_kernel<<<32, 512>>>(out);
}